// round 15
// baseline (speedup 1.0000x reference)
#include <cuda_runtime.h>
#include <cuda_bf16.h>
#include <cstdint>

#define NL 3
#define AST 136                      // padded row stride (bf16 elems)
#define NEG_BIG (-3.402823466e38f)

typedef unsigned int u32;
typedef unsigned short u16;

// Pre-split weight images: [l*2+m][hi=0/lo=1][n*AST + k], bf16, [n][k]
__device__ __align__(16) u16 g_Bimg[NL * 2][2][128 * AST];

__device__ __forceinline__ u32 smaddr(const void* p) {
  u32 a; asm("{ .reg .u64 t; cvta.to.shared.u64 t, %1; cvt.u32.u64 %0, t; }"
             : "=r"(a) : "l"(p));
  return a;
}
__device__ __forceinline__ void ldsm4(u32& r0, u32& r1, u32& r2, u32& r3, u32 a) {
  asm volatile("ldmatrix.sync.aligned.m8n8.x4.shared.b16 {%0,%1,%2,%3}, [%4];"
               : "=r"(r0), "=r"(r1), "=r"(r2), "=r"(r3) : "r"(a));
}
__device__ __forceinline__ void mmab(float* c, const u32* a, u32 b0, u32 b1) {
  asm volatile(
    "mma.sync.aligned.m16n8k16.row.col.f32.bf16.bf16.f32 "
    "{%0,%1,%2,%3}, {%4,%5,%6,%7}, {%8,%9}, {%0,%1,%2,%3};"
    : "+f"(c[0]), "+f"(c[1]), "+f"(c[2]), "+f"(c[3])
    : "r"(a[0]), "r"(a[1]), "r"(a[2]), "r"(a[3]), "r"(b0), "r"(b1));
}
__device__ __forceinline__ void cpa16(u32 dst, const void* src) {
  asm volatile("cp.async.cg.shared.global [%0], [%1], 16;" :: "r"(dst), "l"(src) : "memory");
}
#define CP_COMMIT() asm volatile("cp.async.commit_group;" ::: "memory")
#define CP_WAIT0()  asm volatile("cp.async.wait_group 0;" ::: "memory")

// hi/lo bf16 split (rn rounding, identical to __float2bfloat16)
__device__ __forceinline__ void split2(float f0, float f1, u32& hp, u32& lp) {
  u32 h;
  asm("cvt.rn.bf16x2.f32 %0, %1, %2;" : "=r"(h) : "f"(f1), "f"(f0));
  float h0 = __uint_as_float(h << 16);
  float h1 = __uint_as_float(h & 0xffff0000u);
  float l0 = f0 - h0, l1 = f1 - h1;
  asm("cvt.rn.bf16x2.f32 %0, %1, %2;" : "=r"(lp) : "f"(l1), "f"(l0));
  hp = h;
}

// ---------------- prep: split fp32 weights into bf16 hi/lo [n][k] images ----------------
__global__ void prep_kernel(const float* __restrict__ W1, const float* __restrict__ W2) {
  int id = blockIdx.x * blockDim.x + threadIdx.x;
  if (id >= NL * 2 * 128 * 128) return;
  int n = id & 127, k = (id >> 7) & 127, m = (id >> 14) & 1, l = id >> 15;
  float w = m ? W2[((size_t)l * 256 + k) * 128 + n]
              : W1[((size_t)l * 128 + k) * 128 + n];
  __nv_bfloat16 hi = __float2bfloat16(w);
  __nv_bfloat16 lo = __float2bfloat16(w - __bfloat162float(hi));
  g_Bimg[l * 2 + m][0][n * AST + k] = __bfloat16_as_ushort(hi);
  g_Bimg[l * 2 + m][1][n * AST + k] = __bfloat16_as_ushort(lo);
}

// ---------------- main fused kernel: 1 poly/CTA, 4 warps x (16 rows, 128 cols),
// activations register-chained (GEMM1 D-frag == GEMM2 A-frag), 3 CTAs/SM ----------------
struct Sm {
  u16 B[2][128 * AST];             // hi,lo of current weight matrix (69632 B)
  float pmax[4][128];
  float aggw[128];
  float bias[128], g[128], beta[128];
  unsigned char valid[64];
  int pv;
  u32 det[2];
};

__device__ __forceinline__ void copy_B(u32 dst, const u16* src, int tid) {
  const char* s = reinterpret_cast<const char*>(src);
  #pragma unroll
  for (int i = tid; i < 4352; i += 128) cpa16(dst + i * 16, s + (size_t)i * 16);
}

// 128x128x128 GEMM, A in registers (hh/hl, frag layout), B in smem.
// acc[nt][0..3]: c0=(qr,8nt+2qc) c1=(qr,+1) c2=(qr+8,8nt+2qc) c3=(qr+8,+1)
__device__ __forceinline__ void run_gemm(
    float (*acc)[4], const u32* hh, const u32* hl,
    u32 uBhi, u32 uBlo, u32 boff0)
{
  #pragma unroll
  for (int kt = 0; kt < 8; kt++) {
    const u32* ah = &hh[4 * kt];    // A-frag = D-frags of nt 2kt,2kt+1 (identity)
    const u32* al = &hl[4 * kt];
    #pragma unroll
    for (int p = 0; p < 8; p++) {
      u32 bh[4], bl[4];
      u32 ba = boff0 + (u32)(p * 16 * AST * 2) + (u32)(kt * 32);
      ldsm4(bh[0], bh[1], bh[2], bh[3], uBhi + ba);
      ldsm4(bl[0], bl[1], bl[2], bl[3], uBlo + ba);
      mmab(acc[2 * p],     ah, bh[0], bh[1]);
      mmab(acc[2 * p],     ah, bl[0], bl[1]);
      mmab(acc[2 * p],     al, bh[0], bh[1]);
      mmab(acc[2 * p + 1], ah, bh[2], bh[3]);
      mmab(acc[2 * p + 1], ah, bl[2], bl[3]);
      mmab(acc[2 * p + 1], al, bh[2], bh[3]);
    }
  }
}

__global__ void __launch_bounds__(128, 3) polyreg_kernel(
    const float* __restrict__ x, const unsigned char* __restrict__ mask,
    const float* __restrict__ b1, const float* __restrict__ lng,
    const float* __restrict__ lnb, const float* __restrict__ W2,
    const float* __restrict__ b2, float* __restrict__ out)
{
  extern __shared__ unsigned char smraw[];
  uintptr_t sp = (reinterpret_cast<uintptr_t>(smraw) + 127) & ~(uintptr_t)127;
  Sm& sm = *reinterpret_cast<Sm*>(sp);

  const int tid = threadIdx.x;
  const int wid = tid >> 5, lane = tid & 31;
  const int qr = lane >> 2, qc = lane & 3;
  const int row0 = wid * 16 + qr, row1 = row0 + 8;
  const int poly = blockIdx.x;

  const u32 uBhi = smaddr(sm.B[0]);
  const u32 uBlo = uBhi + 128 * AST * 2;

  // ldmatrix lane-address base for B (proven mapping)
  const int nrow = (lane & 7) + (lane >> 4) * 8;
  const int kcol = ((lane >> 3) & 1) * 8;
  const u32 boff0 = (u32)((nrow * AST + kcol) * 2);

  // kick layer-0 W1 copy immediately (hides behind mask detect + prologue)
  copy_B(uBhi, &g_Bimg[0][0][0], tid);
  CP_COMMIT();

  if (tid == 0) sm.pv = 0;
  if (tid < 2) sm.det[tid] = 0u;
  __syncthreads();

  // ---- mask dtype detection (proven R5/R7/R10) ----
  {
    const u32* mw = reinterpret_cast<const u32*>(mask);
    u32 o123 = 0, o23 = 0;
    for (int j = tid; j < 1024; j += 128) {
      u32 w = mw[j];
      o123 |= (w >> 8);
      o23  |= (w >> 16);
    }
    if (o123) atomicOr(&sm.det[0], o123 & 0xffffffu);
    if (o23)  atomicOr(&sm.det[1], o23 & 0xffffu);
  }
  __syncthreads();
  const int mmode = (sm.det[1] & 0xF0F0u) ? 1 : (sm.det[0] ? 0 : 1);

  if (tid < 64) {
    int midx = poly * 64 + tid;
    unsigned char m;
    if (mmode == 0) m = mask[midx] ? 1 : 0;
    else m = (reinterpret_cast<const u32*>(mask)[midx] != 0u) ? 1 : 0;
    sm.valid[tid] = m;
    if (m) atomicOr(&sm.pv, 1);
  }
  __syncthreads();
  if (tid < 64 && !sm.pv) sm.valid[tid] = 1;   // neutralize fully-invalid poly
  __syncthreads();

  // ---- prologue: x -> hh/hl registers in A-fragment layout ----
  u32 hh[32], hl[32];                  // [nt*2+i]: i=0 row qr, i=1 row qr+8
  {
    const float* xp = x + (size_t)poly * 64 * 128;
    const bool pvok = sm.pv != 0;
    #pragma unroll
    for (int nt = 0; nt < 16; nt++) {
      int c0 = 8 * nt + 2 * qc;
      float2 v0 = make_float2(0.f, 0.f), v1 = v0;
      if (pvok) {
        v0 = *reinterpret_cast<const float2*>(xp + row0 * 128 + c0);
        v1 = *reinterpret_cast<const float2*>(xp + row1 * 128 + c0);
      }
      split2(v0.x, v0.y, hh[nt * 2],     hl[nt * 2]);
      split2(v1.x, v1.y, hh[nt * 2 + 1], hl[nt * 2 + 1]);
    }
  }

  const unsigned char val0 = sm.valid[row0], val1 = sm.valid[row1];
  float acc[16][4];

  for (int l = 0; l < NL; l++) {
    sm.bias[tid] = b1[l * 128 + tid];
    sm.g[tid]    = lng[l * 128 + tid];
    sm.beta[tid] = lnb[l * 128 + tid];
    CP_WAIT0();
    __syncthreads();               // [bar A] B=W1 + params ready

    // ---- GEMM1 (acc init = bias) ----
    #pragma unroll
    for (int nt = 0; nt < 16; nt++) {
      float b0 = sm.bias[8 * nt + 2 * qc], b1v = sm.bias[8 * nt + 2 * qc + 1];
      acc[nt][0] = b0; acc[nt][1] = b1v; acc[nt][2] = b0; acc[nt][3] = b1v;
    }
    run_gemm(acc, hh, hl, uBhi, uBlo, boff0);
    __syncthreads();               // [bar B] all B(W1) reads done

    // issue W2top copy EARLY: drains behind epilogue-1 + GEMV below
    copy_B(uBhi, &g_Bimg[l * 2 + 1][0][0], tid);
    CP_COMMIT();

    // ---- epilogue 1: warp-local LN + ReLU -> hh/hl; masked col-max -> pmax ----
    {
      float s0 = 0.f, q0 = 0.f, s1 = 0.f, q1 = 0.f;
      #pragma unroll
      for (int nt = 0; nt < 16; nt++) {
        s0 += acc[nt][0] + acc[nt][1];
        q0 += acc[nt][0] * acc[nt][0] + acc[nt][1] * acc[nt][1];
        s1 += acc[nt][2] + acc[nt][3];
        q1 += acc[nt][2] * acc[nt][2] + acc[nt][3] * acc[nt][3];
      }
      s0 += __shfl_xor_sync(0xffffffffu, s0, 1); s0 += __shfl_xor_sync(0xffffffffu, s0, 2);
      q0 += __shfl_xor_sync(0xffffffffu, q0, 1); q0 += __shfl_xor_sync(0xffffffffu, q0, 2);
      s1 += __shfl_xor_sync(0xffffffffu, s1, 1); s1 += __shfl_xor_sync(0xffffffffu, s1, 2);
      q1 += __shfl_xor_sync(0xffffffffu, q1, 1); q1 += __shfl_xor_sync(0xffffffffu, q1, 2);
      float mean0 = s0 * (1.f / 128.f);
      float inv0  = rsqrtf(fmaf(q0, 1.f / 128.f, -mean0 * mean0) + 1e-5f);
      float mean1 = s1 * (1.f / 128.f);
      float inv1  = rsqrtf(fmaf(q1, 1.f / 128.f, -mean1 * mean1) + 1e-5f);

      float mx0[16], mx1[16];
      #pragma unroll
      for (int nt = 0; nt < 16; nt++) {
        int c0 = 8 * nt + 2 * qc;
        float gg0 = sm.g[c0], gg1 = sm.g[c0 + 1];
        float bb0 = sm.beta[c0], bb1 = sm.beta[c0 + 1];
        float h0 = fmaxf(fmaf((acc[nt][0] - mean0) * inv0, gg0, bb0), 0.f);
        float h1 = fmaxf(fmaf((acc[nt][1] - mean0) * inv0, gg1, bb1), 0.f);
        float h2 = fmaxf(fmaf((acc[nt][2] - mean1) * inv1, gg0, bb0), 0.f);
        float h3 = fmaxf(fmaf((acc[nt][3] - mean1) * inv1, gg1, bb1), 0.f);
        split2(h0, h1, hh[nt * 2],     hl[nt * 2]);
        split2(h2, h3, hh[nt * 2 + 1], hl[nt * 2 + 1]);
        mx0[nt] = fmaxf(val0 ? h0 : NEG_BIG, val1 ? h2 : NEG_BIG);
        mx1[nt] = fmaxf(val0 ? h1 : NEG_BIG, val1 ? h3 : NEG_BIG);
      }
      #pragma unroll
      for (int nt = 0; nt < 16; nt++) {
        #pragma unroll
        for (int m = 4; m <= 16; m <<= 1) {
          mx0[nt] = fmaxf(mx0[nt], __shfl_xor_sync(0xffffffffu, mx0[nt], m));
          mx1[nt] = fmaxf(mx1[nt], __shfl_xor_sync(0xffffffffu, mx1[nt], m));
        }
      }
      if (qr == 0) {
        #pragma unroll
        for (int nt = 0; nt < 16; nt++) {
          sm.pmax[wid][8 * nt + 2 * qc]     = mx0[nt];
          sm.pmax[wid][8 * nt + 2 * qc + 1] = mx1[nt];
        }
      }
    }
    __syncthreads();               // [bar C] pmax visible

    // ---- GEMV: aggw[e] = b2[e] + (max over warps of pmax)[d] * W2bot[d][e]
    // 8 independent accumulators (MLP 8); overlaps the W2top copy tail.
    {
      const float* wb = W2 + ((size_t)l * 256 + 128) * 128 + tid;
      float a0 = __ldg(&b2[l * 128 + tid]);
      float a1 = 0.f, a2 = 0.f, a3 = 0.f, a4 = 0.f, a5 = 0.f, a6 = 0.f, a7 = 0.f;
      #pragma unroll 4
      for (int d = 0; d < 128; d += 8) {
        float w0 = __ldg(&wb[(size_t)d * 128]);
        float w1 = __ldg(&wb[(size_t)(d + 1) * 128]);
        float w2 = __ldg(&wb[(size_t)(d + 2) * 128]);
        float w3 = __ldg(&wb[(size_t)(d + 3) * 128]);
        float w4 = __ldg(&wb[(size_t)(d + 4) * 128]);
        float w5 = __ldg(&wb[(size_t)(d + 5) * 128]);
        float w6 = __ldg(&wb[(size_t)(d + 6) * 128]);
        float w7 = __ldg(&wb[(size_t)(d + 7) * 128]);
        #define AGG(j) fmaxf(fmaxf(sm.pmax[0][d + j], sm.pmax[1][d + j]), \
                             fmaxf(sm.pmax[2][d + j], sm.pmax[3][d + j]))
        a0 = fmaf(AGG(0), w0, a0);
        a1 = fmaf(AGG(1), w1, a1);
        a2 = fmaf(AGG(2), w2, a2);
        a3 = fmaf(AGG(3), w3, a3);
        a4 = fmaf(AGG(4), w4, a4);
        a5 = fmaf(AGG(5), w5, a5);
        a6 = fmaf(AGG(6), w6, a6);
        a7 = fmaf(AGG(7), w7, a7);
        #undef AGG
      }
      sm.aggw[tid] = ((a0 + a1) + (a2 + a3)) + ((a4 + a5) + (a6 + a7));
    }
    CP_WAIT0();
    __syncthreads();               // [bar D] B=W2top + aggw visible

    // ---- GEMM2 (acc init = aggw: rank-1 term folded in) ----
    #pragma unroll
    for (int nt = 0; nt < 16; nt++) {
      int c0 = 8 * nt + 2 * qc;
      float w0 = sm.aggw[c0], w1 = sm.aggw[c0 + 1];
      acc[nt][0] = w0; acc[nt][1] = w1; acc[nt][2] = w0; acc[nt][3] = w1;
    }
    run_gemm(acc, hh, hl, uBhi, uBlo, boff0);
    __syncthreads();               // [bar E] all B(W2top) reads done

    // ---- epilogue 2 ----
    if (l < NL - 1) {
      copy_B(uBhi, &g_Bimg[(l + 1) * 2][0][0], tid);   // next W1; hides behind split
      CP_COMMIT();
      #pragma unroll
      for (int nt = 0; nt < 16; nt++) {
        split2(acc[nt][0], acc[nt][1], hh[nt * 2],     hl[nt * 2]);
        split2(acc[nt][2], acc[nt][3], hh[nt * 2 + 1], hl[nt * 2 + 1]);
      }
    } else {
      float mx0[16], mx1[16];
      #pragma unroll
      for (int nt = 0; nt < 16; nt++) {
        mx0[nt] = fmaxf(val0 ? acc[nt][0] : NEG_BIG, val1 ? acc[nt][2] : NEG_BIG);
        mx1[nt] = fmaxf(val0 ? acc[nt][1] : NEG_BIG, val1 ? acc[nt][3] : NEG_BIG);
      }
      #pragma unroll
      for (int nt = 0; nt < 16; nt++) {
        #pragma unroll
        for (int m = 4; m <= 16; m <<= 1) {
          mx0[nt] = fmaxf(mx0[nt], __shfl_xor_sync(0xffffffffu, mx0[nt], m));
          mx1[nt] = fmaxf(mx1[nt], __shfl_xor_sync(0xffffffffu, mx1[nt], m));
        }
      }
      if (qr == 0) {
        #pragma unroll
        for (int nt = 0; nt < 16; nt++) {
          sm.pmax[wid][8 * nt + 2 * qc]     = mx0[nt];
          sm.pmax[wid][8 * nt + 2 * qc + 1] = mx1[nt];
        }
      }
      __syncthreads();
      // aggw already inside acc -> max includes it
      float m = fmaxf(fmaxf(sm.pmax[0][tid], sm.pmax[1][tid]),
                      fmaxf(sm.pmax[2][tid], sm.pmax[3][tid]));
      if (!sm.pv) m = 0.f;
      out[(size_t)poly * 128 + tid] = m;
    }
  }
}

extern "C" void kernel_launch(void* const* d_in, const int* in_sizes, int n_in,
                              void* d_out, int out_size) {
  const float*         x    = (const float*)d_in[0];
  const unsigned char* mask = (const unsigned char*)d_in[1];
  const float*         W1   = (const float*)d_in[2];
  const float*         b1   = (const float*)d_in[3];
  const float*         lng  = (const float*)d_in[4];
  const float*         lnb  = (const float*)d_in[5];
  const float*         W2   = (const float*)d_in[6];
  const float*         b2   = (const float*)d_in[7];
  float* out = (float*)d_out;

  int smem = (int)sizeof(Sm) + 128;
  (void)cudaFuncSetAttribute(polyreg_kernel,
                             cudaFuncAttributeMaxDynamicSharedMemorySize, smem);

  prep_kernel<<<(NL * 2 * 128 * 128 + 255) / 256, 256>>>(W1, W2);
  polyreg_kernel<<<2048, 128, smem>>>(x, mask, b1, lng, lnb, W2, b2, out);
}